// round 5
// baseline (speedup 1.0000x reference)
#include <cuda_runtime.h>
#include <cuda_fp16.h>

#define NN 102400
#define EE 1638400
#define ET (EE + NN)   // edges incl self loops
#define GG 256
#define FULL 0xffffffffu

// ---------------- scratch (device globals; no allocation) ----------------
__device__ __align__(16) __half g_h1h[NN * 128];   // layer1 projected features (fp16)
__device__ __align__(16) float  g_als1[NN * 4];
__device__ __align__(16) float  g_ald1[NN * 4];
__device__ __align__(16) __half g_h2h[NN * 32];    // layer2 projected features (fp16)
__device__ __align__(16) float  g_als2[NN];
__device__ __align__(16) float  g_ald2[NN];
__device__ __align__(16) int    g_cnt[NN];
__device__ __align__(16) int    g_rowptr[NN + 4];
__device__ __align__(16) int    g_pos[NN];
__device__ __align__(16) int    g_csr[ET];
__device__ __align__(16) float  g_pool[GG * 32];

__device__ __forceinline__ float eluf(float v) {
    return (v > 0.f) ? v : (__expf(v) - 1.f);
}
__device__ __forceinline__ float lrelu(float e) {
    return (e > 0.f) ? e : 0.2f * e;
}

// ---------------- CSR build ----------------
__global__ void k_init() {
    int i = blockIdx.x * blockDim.x + threadIdx.x;
    if (i < NN) g_cnt[i] = 1;          // self loop pre-counted
    if (i < GG * 32) g_pool[i] = 0.f;
}

__global__ void k_hist(const int* __restrict__ ei) {
    int t = blockIdx.x * blockDim.x + threadIdx.x;
    if (t < EE / 4) {
        int4 d4 = ((const int4*)(ei + EE))[t];
        atomicAdd(&g_cnt[d4.x], 1);
        atomicAdd(&g_cnt[d4.y], 1);
        atomicAdd(&g_cnt[d4.z], 1);
        atomicAdd(&g_cnt[d4.w], 1);
    }
}

// single block, 1024 threads, 100 elements each (1024*100 == NN)
__global__ void k_scan() {
    __shared__ int sp[1024];
    int t = threadIdx.x;
    const int4* cv = (const int4*)(g_cnt + t * 100);
    int s = 0;
#pragma unroll
    for (int i = 0; i < 25; i++) {
        int4 c = cv[i];
        s += c.x + c.y + c.z + c.w;
    }
    sp[t] = s;
    __syncthreads();
    for (int off = 1; off < 1024; off <<= 1) {
        int v = (t >= off) ? sp[t - off] : 0;
        __syncthreads();
        sp[t] += v;
        __syncthreads();
    }
    int run = t ? sp[t - 1] : 0;
    int4* rp = (int4*)(g_rowptr + t * 100);
    int4* pp = (int4*)(g_pos + t * 100);
#pragma unroll
    for (int i = 0; i < 25; i++) {
        int4 c = cv[i];
        int4 r;
        r.x = run; run += c.x;
        r.y = run; run += c.y;
        r.z = run; run += c.z;
        r.w = run; run += c.w;
        rp[i] = r;
        pp[i] = r;
    }
    if (t == 1023) g_rowptr[NN] = ET;
}

__global__ void k_scatter(const int* __restrict__ ei) {
    int t = blockIdx.x * blockDim.x + threadIdx.x;
    const int Q = EE / 4;
    if (t < Q) {
        int4 s4 = ((const int4*)ei)[t];
        int4 d4 = ((const int4*)(ei + EE))[t];
        int p;
        p = atomicAdd(&g_pos[d4.x], 1); g_csr[p] = s4.x;
        p = atomicAdd(&g_pos[d4.y], 1); g_csr[p] = s4.y;
        p = atomicAdd(&g_pos[d4.z], 1); g_csr[p] = s4.z;
        p = atomicAdd(&g_pos[d4.w], 1); g_csr[p] = s4.w;
    } else {
        int n = t - Q;
        if (n < NN) {
            int p = atomicAdd(&g_pos[n], 1);
            g_csr[p] = n;
        }
    }
}

// ---------------- gemm1: h1 = x @ W1 (fp16 out) + attn logits ----------------
__global__ void k_gemm1(const float* __restrict__ x,
                        const float* __restrict__ W1,
                        const float* __restrict__ a_src1,
                        const float* __restrict__ a_dst1) {
    __shared__ float xs[16 * 64];
    int col = threadIdx.x;                 // output column 0..127
    float w[64];
#pragma unroll
    for (int k = 0; k < 64; k++) w[k] = W1[k * 128 + col];
    float asw = a_src1[col], adw = a_dst1[col];
    int node0 = blockIdx.x * 16;
    for (int j = threadIdx.x; j < 16 * 64; j += 128) xs[j] = x[node0 * 64 + j];
    __syncthreads();
    int lane = col & 31, wp = col >> 5;    // wp == head
    for (int nl = 0; nl < 16; nl++) {
        float acc = 0.f;
        const float4* xv = (const float4*)&xs[nl * 64];
#pragma unroll
        for (int k4 = 0; k4 < 16; k4++) {
            float4 xx = xv[k4];
            acc += xx.x * w[4 * k4 + 0];
            acc += xx.y * w[4 * k4 + 1];
            acc += xx.z * w[4 * k4 + 2];
            acc += xx.w * w[4 * k4 + 3];
        }
        int n = node0 + nl;
        float other = __shfl_xor_sync(FULL, acc, 1);
        if (!(col & 1))
            ((__half2*)g_h1h)[(n * 128 + col) >> 1] = __floats2half2_rn(acc, other);
        float ps = acc * asw, pd = acc * adw;
#pragma unroll
        for (int off = 16; off; off >>= 1) {
            ps += __shfl_xor_sync(FULL, ps, off);
            pd += __shfl_xor_sync(FULL, pd, off);
        }
        if (lane == 0) {
            g_als1[n * 4 + wp] = ps;
            g_ald1[n * 4 + wp] = pd;
        }
    }
}

// ---------------- fused: gather layer1 + normalize + ELU + GEMM2 + logits2 ----------------
// warp per 4 dst nodes; 8 warps/block.
// Edge loop: software-pipelined batches of 8 (next batch's indices load while
// current batch's rows are in flight).
__global__ void __launch_bounds__(256, 3) k_edge1(const float* __restrict__ W2,
                                                  const float* __restrict__ b1,
                                                  const float* __restrict__ a2s,
                                                  const float* __restrict__ a2d) {
    __shared__ float sWt[32 * 132];   // sWt[c*132 + k] = W2[k][c], padded
    __shared__ float sb[128];
    int tid = threadIdx.x;
    for (int j = tid; j < 4096; j += 256) {
        int k = j >> 5, c = j & 31;
        sWt[c * 132 + k] = W2[j];
    }
    if (tid < 128) sb[tid] = b1[tid];
    __syncthreads();

    int lane = tid & 31;
    int warp = (blockIdx.x << 3) + (tid >> 5);
    int d0 = warp * 4;
    int head = lane >> 3;

    const float2* h1v = (const float2*)g_h1h;

    float4 a[4];
#pragma unroll
    for (int n = 0; n < 4; n++) {
        int d = d0 + n;
        float ald = g_ald1[4 * d + head];
        int beg = g_rowptr[d], end = g_rowptr[d + 1];
        float4 acc = make_float4(0.f, 0.f, 0.f, 0.f);
        float den = 0.f;
        int pad = g_csr[beg];           // always valid (>=1 edge: self loop)

        int s[8];
        int j = beg;
#pragma unroll
        for (int t = 0; t < 8; t++)
            s[t] = (j + t < end) ? g_csr[j + t] : pad;

        while (j < end) {
            int nb = j + 8;
            // issue all loads for current batch (independent)
            float l[8];
            float2 r[8];
#pragma unroll
            for (int t = 0; t < 8; t++) l[t] = g_als1[4 * s[t] + head];
#pragma unroll
            for (int t = 0; t < 8; t++) r[t] = h1v[(s[t] << 5) + lane];
            // prefetch next batch indices (overlaps row latency)
            int ns[8];
#pragma unroll
            for (int t = 0; t < 8; t++)
                ns[t] = (nb + t < end) ? g_csr[nb + t] : pad;
            // consume
#pragma unroll
            for (int t = 0; t < 8; t++) {
                float wv = (j + t < end) ? __expf(lrelu(l[t] + ald)) : 0.f;
                den += wv;
                float2 f0 = __half22float2(*(__half2*)&r[t].x);
                float2 f1 = __half22float2(*(__half2*)&r[t].y);
                acc.x += wv * f0.x;
                acc.y += wv * f0.y;
                acc.z += wv * f1.x;
                acc.w += wv * f1.y;
            }
#pragma unroll
            for (int t = 0; t < 8; t++) s[t] = ns[t];
            j = nb;
        }
        float inv = 1.f / den;
        float4 bb = *(const float4*)&sb[lane * 4];
        a[n].x = eluf(acc.x * inv + bb.x);
        a[n].y = eluf(acc.y * inv + bb.y);
        a[n].z = eluf(acc.z * inv + bb.z);
        a[n].w = eluf(acc.w * inv + bb.w);
    }

    // shuffle GEMM: o[n][col=lane] = sum_k a[n][k] * W2[k][lane]
    float o[4] = {0.f, 0.f, 0.f, 0.f};
#pragma unroll
    for (int sl = 0; sl < 32; sl++) {
        float4 w4 = *(const float4*)&sWt[lane * 132 + 4 * sl];
#pragma unroll
        for (int n = 0; n < 4; n++) {
            float ax = __shfl_sync(FULL, a[n].x, sl);
            float ay = __shfl_sync(FULL, a[n].y, sl);
            float az = __shfl_sync(FULL, a[n].z, sl);
            float aw = __shfl_sync(FULL, a[n].w, sl);
            o[n] += ax * w4.x + ay * w4.y + az * w4.z + aw * w4.w;
        }
    }

    float als = a2s[lane], aldv = a2d[lane];
#pragma unroll
    for (int n = 0; n < 4; n++) {
        g_h2h[(d0 + n) * 32 + lane] = __float2half(o[n]);
        float ps = o[n] * als, pd = o[n] * aldv;
#pragma unroll
        for (int off = 16; off; off >>= 1) {
            ps += __shfl_xor_sync(FULL, ps, off);
            pd += __shfl_xor_sync(FULL, pd, off);
        }
        if (lane == 0) {
            g_als2[d0 + n] = ps;
            g_ald2[d0 + n] = pd;
        }
    }
}

// ---------------- layer2 gather + ELU + pooled reduction ----------------
// warp per dst node; half-warp per edge, pipelined batches of 8 edges.
__global__ void __launch_bounds__(256) k_edge2(const float* __restrict__ b2) {
    int lane = threadIdx.x & 31;
    int d = (blockIdx.x << 3) + (threadIdx.x >> 5);
    int hw = lane >> 4;            // which edge of a pair
    int c2 = (lane & 15) << 1;     // column base (2 cols per lane)
    float ald = g_ald2[d];
    int beg = g_rowptr[d], end = g_rowptr[d + 1];
    int pad = g_csr[beg];
    float ax = 0.f, ay = 0.f, den = 0.f;

    int s[4];
    int j = beg;
#pragma unroll
    for (int t = 0; t < 4; t++) {
        int jj = j + 2 * t + hw;
        s[t] = (jj < end) ? g_csr[jj] : pad;
    }
    while (j < end) {
        int nb = j + 8;
        float l[4];
        __half2 v[4];
#pragma unroll
        for (int t = 0; t < 4; t++) l[t] = g_als2[s[t]];
#pragma unroll
        for (int t = 0; t < 4; t++) v[t] = *(const __half2*)(g_h2h + s[t] * 32 + c2);
        int ns[4];
#pragma unroll
        for (int t = 0; t < 4; t++) {
            int jj = nb + 2 * t + hw;
            ns[t] = (jj < end) ? g_csr[jj] : pad;
        }
#pragma unroll
        for (int t = 0; t < 4; t++) {
            bool valid = (j + 2 * t + hw) < end;
            float wv = valid ? __expf(lrelu(l[t] + ald)) : 0.f;
            den += wv;
            float2 f = __half22float2(v[t]);
            ax += wv * f.x;
            ay += wv * f.y;
        }
#pragma unroll
        for (int t = 0; t < 4; t++) s[t] = ns[t];
        j = nb;
    }
    den += __shfl_xor_sync(FULL, den, 16);
    ax  += __shfl_xor_sync(FULL, ax, 16);
    ay  += __shfl_xor_sync(FULL, ay, 16);
    if (hw == 0) {
        float inv = 1.f / den;
        float vx = eluf(ax * inv + b2[c2]);
        float vy = eluf(ay * inv + b2[c2 + 1]);
        int g = d / 400;
        atomicAdd(&g_pool[g * 32 + c2], vx);
        atomicAdd(&g_pool[g * 32 + c2 + 1], vy);
    }
}

// ---------------- classifier MLP ----------------
__global__ void k_mlp(const float* __restrict__ clinical,
                      const float* __restrict__ Wc1,
                      const float* __restrict__ bc1,
                      const float* __restrict__ Wc2,
                      const float* __restrict__ bc2,
                      float* __restrict__ out) {
    int g = blockIdx.x;
    int t = threadIdx.x;   // 64
    __shared__ float sf[37];
    __shared__ float sz[16];
    if (t < 32) sf[t] = g_pool[g * 32 + t] * (1.f / 400.f);
    else if (t < 37) sf[t] = clinical[g * 5 + (t - 32)];
    __syncthreads();
    if (t < 16) {
        float z = bc1[t];
#pragma unroll
        for (int i = 0; i < 37; i++) z += sf[i] * Wc1[i * 16 + t];
        sz[t] = eluf(z);
    }
    __syncthreads();
    if (t == 0) {
        float o = bc2[0];
#pragma unroll
        for (int j = 0; j < 16; j++) o += sz[j] * Wc2[j];
        out[g] = o;
    }
}

// ---------------- launch ----------------
extern "C" void kernel_launch(void* const* d_in, const int* in_sizes, int n_in,
                              void* d_out, int out_size) {
    const float* x        = (const float*)d_in[0];
    const int*   ei       = (const int*)d_in[1];
    const float* clinical = (const float*)d_in[3];
    const float* W1       = (const float*)d_in[4];
    const float* a_src1   = (const float*)d_in[5];
    const float* a_dst1   = (const float*)d_in[6];
    const float* b1       = (const float*)d_in[7];
    const float* W2       = (const float*)d_in[8];
    const float* a_src2   = (const float*)d_in[9];
    const float* a_dst2   = (const float*)d_in[10];
    const float* b2       = (const float*)d_in[11];
    const float* Wc1      = (const float*)d_in[12];
    const float* bc1      = (const float*)d_in[13];
    const float* Wc2      = (const float*)d_in[14];
    const float* bc2      = (const float*)d_in[15];
    float* out = (float*)d_out;

    k_init<<<(NN + 255) / 256, 256>>>();
    k_hist<<<(EE / 4 + 255) / 256, 256>>>(ei);
    k_scan<<<1, 1024>>>();
    k_scatter<<<(EE / 4 + NN + 255) / 256, 256>>>(ei);
    k_gemm1<<<NN / 16, 128>>>(x, W1, a_src1, a_dst1);
    k_edge1<<<NN / 32, 256>>>(W2, b1, a_src2, a_dst2);
    k_edge2<<<NN / 8, 256>>>(b2);
    k_mlp<<<GG, 64>>>(clinical, Wc1, bc1, Wc2, bc2, out);
}

// round 6
// speedup vs baseline: 1.0600x; 1.0600x over previous
#include <cuda_runtime.h>
#include <cuda_fp16.h>

#define NN 102400
#define EE 1638400
#define ET (EE + NN)   // edges incl self loops
#define GG 256
#define FULL 0xffffffffu

// ---------------- scratch (device globals; no allocation) ----------------
__device__ __align__(16) __half g_h1h[NN * 128];   // layer1 projected features (fp16)
__device__ __align__(16) float  g_als1[NN * 4];
__device__ __align__(16) float  g_ald1[NN * 4];
__device__ __align__(16) __half g_h2h[NN * 32];    // layer2 projected features (fp16)
__device__ __align__(16) float  g_als2[NN];
__device__ __align__(16) float  g_ald2[NN];
__device__ __align__(16) int    g_cnt[NN];
__device__ __align__(16) int    g_rowptr[NN + 4];
__device__ __align__(16) int    g_pos[NN];
__device__ __align__(16) int    g_csr[ET];
__device__ __align__(16) float  g_pool[GG * 32];

__device__ __forceinline__ float eluf(float v) {
    return (v > 0.f) ? v : (__expf(v) - 1.f);
}
__device__ __forceinline__ float lrelu(float e) {
    return (e > 0.f) ? e : 0.2f * e;
}

// ---------------- CSR build ----------------
__global__ void k_init() {
    int i = blockIdx.x * blockDim.x + threadIdx.x;
    if (i < NN) g_cnt[i] = 1;          // self loop pre-counted
    if (i < GG * 32) g_pool[i] = 0.f;
}

__global__ void k_hist(const int* __restrict__ ei) {
    int t = blockIdx.x * blockDim.x + threadIdx.x;
    if (t < EE / 4) {
        int4 d4 = ((const int4*)(ei + EE))[t];
        atomicAdd(&g_cnt[d4.x], 1);
        atomicAdd(&g_cnt[d4.y], 1);
        atomicAdd(&g_cnt[d4.z], 1);
        atomicAdd(&g_cnt[d4.w], 1);
    }
}

// single block, 1024 threads, 100 elements each (1024*100 == NN)
__global__ void k_scan() {
    __shared__ int sp[1024];
    int t = threadIdx.x;
    const int4* cv = (const int4*)(g_cnt + t * 100);
    int s = 0;
#pragma unroll
    for (int i = 0; i < 25; i++) {
        int4 c = cv[i];
        s += c.x + c.y + c.z + c.w;
    }
    sp[t] = s;
    __syncthreads();
    for (int off = 1; off < 1024; off <<= 1) {
        int v = (t >= off) ? sp[t - off] : 0;
        __syncthreads();
        sp[t] += v;
        __syncthreads();
    }
    int run = t ? sp[t - 1] : 0;
    int4* rp = (int4*)(g_rowptr + t * 100);
    int4* pp = (int4*)(g_pos + t * 100);
#pragma unroll
    for (int i = 0; i < 25; i++) {
        int4 c = cv[i];
        int4 r;
        r.x = run; run += c.x;
        r.y = run; run += c.y;
        r.z = run; run += c.z;
        r.w = run; run += c.w;
        rp[i] = r;
        pp[i] = r;
    }
    if (t == 1023) g_rowptr[NN] = ET;
}

__global__ void k_scatter(const int* __restrict__ ei) {
    int t = blockIdx.x * blockDim.x + threadIdx.x;
    const int Q = EE / 4;
    if (t < Q) {
        int4 s4 = ((const int4*)ei)[t];
        int4 d4 = ((const int4*)(ei + EE))[t];
        int p;
        p = atomicAdd(&g_pos[d4.x], 1); g_csr[p] = s4.x;
        p = atomicAdd(&g_pos[d4.y], 1); g_csr[p] = s4.y;
        p = atomicAdd(&g_pos[d4.z], 1); g_csr[p] = s4.z;
        p = atomicAdd(&g_pos[d4.w], 1); g_csr[p] = s4.w;
    } else {
        int n = t - Q;
        if (n < NN) {
            int p = atomicAdd(&g_pos[n], 1);
            g_csr[p] = n;
        }
    }
}

// ---------------- gemm1: h1 = x @ W1 (fp16 out) + attn logits ----------------
__global__ void k_gemm1(const float* __restrict__ x,
                        const float* __restrict__ W1,
                        const float* __restrict__ a_src1,
                        const float* __restrict__ a_dst1) {
    __shared__ float xs[16 * 64];
    int col = threadIdx.x;                 // output column 0..127
    float w[64];
#pragma unroll
    for (int k = 0; k < 64; k++) w[k] = W1[k * 128 + col];
    float asw = a_src1[col], adw = a_dst1[col];
    int node0 = blockIdx.x * 16;
    for (int j = threadIdx.x; j < 16 * 64; j += 128) xs[j] = x[node0 * 64 + j];
    __syncthreads();
    int lane = col & 31, wp = col >> 5;    // wp == head
    for (int nl = 0; nl < 16; nl++) {
        float acc = 0.f;
        const float4* xv = (const float4*)&xs[nl * 64];
#pragma unroll
        for (int k4 = 0; k4 < 16; k4++) {
            float4 xx = xv[k4];
            acc += xx.x * w[4 * k4 + 0];
            acc += xx.y * w[4 * k4 + 1];
            acc += xx.z * w[4 * k4 + 2];
            acc += xx.w * w[4 * k4 + 3];
        }
        int n = node0 + nl;
        float other = __shfl_xor_sync(FULL, acc, 1);
        if (!(col & 1))
            ((__half2*)g_h1h)[(n * 128 + col) >> 1] = __floats2half2_rn(acc, other);
        float ps = acc * asw, pd = acc * adw;
#pragma unroll
        for (int off = 16; off; off >>= 1) {
            ps += __shfl_xor_sync(FULL, ps, off);
            pd += __shfl_xor_sync(FULL, pd, off);
        }
        if (lane == 0) {
            g_als1[n * 4 + wp] = ps;
            g_ald1[n * 4 + wp] = pd;
        }
    }
}

// ---------------- fused: gather layer1 + normalize + ELU + GEMM2 + logits2 ----------------
// ONE dst node per warp; 8 warps/block; batch-4 edge gather.
// GEMM2 uses per-lane register copy of W2 column (no shared, no bank conflicts).
__global__ void __launch_bounds__(256) k_edge1(const float* __restrict__ W2,
                                               const float* __restrict__ b1,
                                               const float* __restrict__ a2s,
                                               const float* __restrict__ a2d) {
    int tid = threadIdx.x;
    int lane = tid & 31;
    int d = (blockIdx.x << 3) + (tid >> 5);   // node id (grid = NN/8)
    int head = lane >> 3;

    const float2* h1v = (const float2*)g_h1h;

    float ald = g_ald1[4 * d + head];
    int beg = g_rowptr[d], end = g_rowptr[d + 1];
    int pad = g_csr[beg];                 // valid (self loop guarantees >=1)
    float4 acc = make_float4(0.f, 0.f, 0.f, 0.f);
    float den = 0.f;

    for (int j = beg; j < end; j += 4) {
        int s0 = (j     < end) ? g_csr[j]     : pad;
        int s1 = (j + 1 < end) ? g_csr[j + 1] : pad;
        int s2 = (j + 2 < end) ? g_csr[j + 2] : pad;
        int s3 = (j + 3 < end) ? g_csr[j + 3] : pad;
        float l0 = g_als1[4 * s0 + head];
        float l1 = g_als1[4 * s1 + head];
        float l2 = g_als1[4 * s2 + head];
        float l3 = g_als1[4 * s3 + head];
        float2 r0 = h1v[(s0 << 5) + lane];
        float2 r1 = h1v[(s1 << 5) + lane];
        float2 r2 = h1v[(s2 << 5) + lane];
        float2 r3 = h1v[(s3 << 5) + lane];
        float w0 = (j     < end) ? __expf(lrelu(l0 + ald)) : 0.f;
        float w1 = (j + 1 < end) ? __expf(lrelu(l1 + ald)) : 0.f;
        float w2 = (j + 2 < end) ? __expf(lrelu(l2 + ald)) : 0.f;
        float w3 = (j + 3 < end) ? __expf(lrelu(l3 + ald)) : 0.f;
        den += (w0 + w1) + (w2 + w3);
        float2 f;
#define ACC4(R, W)                                          \
        f = __half22float2(*(__half2*)&(R).x);              \
        acc.x += (W) * f.x; acc.y += (W) * f.y;             \
        f = __half22float2(*(__half2*)&(R).y);              \
        acc.z += (W) * f.x; acc.w += (W) * f.y;
        ACC4(r0, w0) ACC4(r1, w1) ACC4(r2, w2) ACC4(r3, w3)
#undef ACC4
    }

    float inv = 1.f / den;
    float4 bb = *(const float4*)&b1[lane * 4];   // L1-cached, broadcast-ish
    float4 a;
    a.x = eluf(acc.x * inv + bb.x);
    a.y = eluf(acc.y * inv + bb.y);
    a.z = eluf(acc.z * inv + bb.z);
    a.w = eluf(acc.w * inv + bb.w);

    // per-lane W2 column in registers (loaded after gather: disjoint lifetime)
    float w[32];
#pragma unroll
    for (int k = 0; k < 32; k++) w[k] = W2[((k << 2)) * 32 + lane];   // rows 4k
    // note: need all 128 rows; pull remaining via 4-row groups below
    // w[k] holds W2[4k][lane]; fetch the other 3 rows inside the loop from L1.

    float o = 0.f;
#pragma unroll
    for (int sl = 0; sl < 32; sl++) {
        float ax = __shfl_sync(FULL, a.x, sl);
        float ay = __shfl_sync(FULL, a.y, sl);
        float az = __shfl_sync(FULL, a.z, sl);
        float aw = __shfl_sync(FULL, a.w, sl);
        float w0 = w[sl];
        float w1 = W2[(4 * sl + 1) * 32 + lane];
        float w2 = W2[(4 * sl + 2) * 32 + lane];
        float w3 = W2[(4 * sl + 3) * 32 + lane];
        o += ax * w0 + ay * w1 + az * w2 + aw * w3;
    }

    g_h2h[d * 32 + lane] = __float2half(o);
    float ps = o * a2s[lane], pd = o * a2d[lane];
#pragma unroll
    for (int off = 16; off; off >>= 1) {
        ps += __shfl_xor_sync(FULL, ps, off);
        pd += __shfl_xor_sync(FULL, pd, off);
    }
    if (lane == 0) {
        g_als2[d] = ps;
        g_ald2[d] = pd;
    }
}

// ---------------- layer2 gather + ELU + pooled reduction ----------------
// warp per dst node, half-warp per edge, unrolled x2 (4 edges in flight).
__global__ void __launch_bounds__(256) k_edge2(const float* __restrict__ b2) {
    int lane = threadIdx.x & 31;
    int d = (blockIdx.x << 3) + (threadIdx.x >> 5);
    int hw = lane >> 4;            // which edge of the pair
    int c2 = (lane & 15) << 1;     // column base (2 cols per lane)
    float ald = g_ald2[d];
    int beg = g_rowptr[d], end = g_rowptr[d + 1];
    float ax = 0.f, ay = 0.f, den = 0.f;
    int j = beg;
    for (; j + 4 <= end; j += 4) {
        int s0 = g_csr[j + hw];
        int s1 = g_csr[j + 2 + hw];
        float l0 = g_als2[s0];
        float l1 = g_als2[s1];
        __half2 v0 = *(const __half2*)(g_h2h + s0 * 32 + c2);
        __half2 v1 = *(const __half2*)(g_h2h + s1 * 32 + c2);
        float w0 = __expf(lrelu(l0 + ald));
        float w1 = __expf(lrelu(l1 + ald));
        den += w0 + w1;
        float2 f0 = __half22float2(v0);
        float2 f1 = __half22float2(v1);
        ax += w0 * f0.x + w1 * f1.x;
        ay += w0 * f0.y + w1 * f1.y;
    }
    for (; j < end; j += 2) {
        int jj = j + hw;
        bool valid = jj < end;
        int s = g_csr[valid ? jj : beg];
        float e = lrelu(g_als2[s] + ald);
        float wv = valid ? __expf(e) : 0.f;
        den += wv;
        __half2 hv = *(const __half2*)(g_h2h + s * 32 + c2);
        float2 f = __half22float2(hv);
        ax += wv * f.x;
        ay += wv * f.y;
    }
    den += __shfl_xor_sync(FULL, den, 16);
    ax  += __shfl_xor_sync(FULL, ax, 16);
    ay  += __shfl_xor_sync(FULL, ay, 16);
    if (hw == 0) {
        float inv = 1.f / den;
        float vx = eluf(ax * inv + b2[c2]);
        float vy = eluf(ay * inv + b2[c2 + 1]);
        int g = d / 400;
        atomicAdd(&g_pool[g * 32 + c2], vx);
        atomicAdd(&g_pool[g * 32 + c2 + 1], vy);
    }
}

// ---------------- classifier MLP ----------------
__global__ void k_mlp(const float* __restrict__ clinical,
                      const float* __restrict__ Wc1,
                      const float* __restrict__ bc1,
                      const float* __restrict__ Wc2,
                      const float* __restrict__ bc2,
                      float* __restrict__ out) {
    int g = blockIdx.x;
    int t = threadIdx.x;   // 64
    __shared__ float sf[37];
    __shared__ float sz[16];
    if (t < 32) sf[t] = g_pool[g * 32 + t] * (1.f / 400.f);
    else if (t < 37) sf[t] = clinical[g * 5 + (t - 32)];
    __syncthreads();
    if (t < 16) {
        float z = bc1[t];
#pragma unroll
        for (int i = 0; i < 37; i++) z += sf[i] * Wc1[i * 16 + t];
        sz[t] = eluf(z);
    }
    __syncthreads();
    if (t == 0) {
        float o = bc2[0];
#pragma unroll
        for (int j = 0; j < 16; j++) o += sz[j] * Wc2[j];
        out[g] = o;
    }
}

// ---------------- launch ----------------
extern "C" void kernel_launch(void* const* d_in, const int* in_sizes, int n_in,
                              void* d_out, int out_size) {
    const float* x        = (const float*)d_in[0];
    const int*   ei       = (const int*)d_in[1];
    const float* clinical = (const float*)d_in[3];
    const float* W1       = (const float*)d_in[4];
    const float* a_src1   = (const float*)d_in[5];
    const float* a_dst1   = (const float*)d_in[6];
    const float* b1       = (const float*)d_in[7];
    const float* W2       = (const float*)d_in[8];
    const float* a_src2   = (const float*)d_in[9];
    const float* a_dst2   = (const float*)d_in[10];
    const float* b2       = (const float*)d_in[11];
    const float* Wc1      = (const float*)d_in[12];
    const float* bc1      = (const float*)d_in[13];
    const float* Wc2      = (const float*)d_in[14];
    const float* bc2      = (const float*)d_in[15];
    float* out = (float*)d_out;

    k_init<<<(NN + 255) / 256, 256>>>();
    k_hist<<<(EE / 4 + 255) / 256, 256>>>(ei);
    k_scan<<<1, 1024>>>();
    k_scatter<<<(EE / 4 + NN + 255) / 256, 256>>>(ei);
    k_gemm1<<<NN / 16, 128>>>(x, W1, a_src1, a_dst1);
    k_edge1<<<NN / 8, 256>>>(W2, b1, a_src2, a_dst2);
    k_edge2<<<NN / 8, 256>>>(b2);
    k_mlp<<<GG, 64>>>(clinical, Wc1, bc1, Wc2, bc2, out);
}